// round 12
// baseline (speedup 1.0000x reference)
#include <cuda_runtime.h>
#include <math.h>

#define BB 64
#define NN 17
#define CC 32
#define HW 4096   // 64*64

#define OFF_J 0           // joints: 64*17*2 = 2176
#define OFF_V 2176        // valid:  64*17   = 1088
#define OFF_K 3264        // new_keys: 64*17*32 = 34816
#define OFF_D 38080       // dist_x4: 64*17*256*256 = 71303168

__device__ float g_wdist[(size_t)BB * NN * HW];

// Proven-equal closed form of the 15-move ring weight (validated round 11):
//   M = max(dx,dy); w = 0.5+0.25*M for 1<=M<=15;
//   M==0 -> 0.75 iff keypoint on any border else 10; M>15 -> 10.
__device__ __forceinline__ float weight_at(int x, int y, int kx, int ky) {
    int dx = abs(x - kx), dy = abs(y - ky);
    int M = max(dx, dy);
    bool border = (kx == 0) | (kx == 63) | (ky == 0) | (ky == 63);
    if (M == 0) return border ? 0.75f : 10.0f;
    return (M <= 15) ? fmaf(0.25f, (float)M, 0.5f) : 10.0f;
}

// ---------------- Kernel A: wdist (B,N,64,64) ---------------- (round-6 structure)
__global__ void __launch_bounds__(512) kA(const float* __restrict__ q,
                                          const float* __restrict__ keys,
                                          const int*   __restrict__ joints) {
    const int b = blockIdx.y;
    const int p = blockIdx.x * 512 + threadIdx.x;
    __shared__ __align__(16) float skey[NN][CC];
    __shared__ float sk2[NN];
    __shared__ int   skx[NN], sky[NN];
    const int t = threadIdx.x;
    if (t < NN * CC / 4)
        reinterpret_cast<float4*>(skey)[t] =
            reinterpret_cast<const float4*>(keys + b * NN * CC)[t];
    __syncthreads();
    if (t < NN) {
        float s = 0.f;   // mul+add sequential, no fma (XLA-faithful)
        for (int c = 0; c < CC; c++) s = __fadd_rn(s, __fmul_rn(skey[t][c], skey[t][c]));
        sk2[t] = s;
        skx[t] = joints[(b * NN + t) * 2 + 0];
        sky[t] = joints[(b * NN + t) * 2 + 1];
    }
    __syncthreads();

    float qv[CC];
    const float* qb = q + (size_t)b * CC * HW + p;
    float q2 = 0.f;
#pragma unroll
    for (int c = 0; c < CC; c++) {
        qv[c] = qb[(size_t)c * HW];
        q2 = __fadd_rn(q2, __fmul_rn(qv[c], qv[c]));
    }

    const int y = p >> 6, x = p & 63;
    float* wout = g_wdist + ((size_t)b * NN) * HW + p;
#pragma unroll 1
    for (int n = 0; n < NN; n++) {
        const float4* k4 = reinterpret_cast<const float4*>(skey[n]);
        float dot = 0.f;   // sequential ascending-c fmaf (gemm-faithful)
#pragma unroll
        for (int c4 = 0; c4 < CC / 4; c4++) {
            float4 kk = k4[c4];
            dot = fmaf(kk.x, qv[4 * c4 + 0], dot);
            dot = fmaf(kk.y, qv[4 * c4 + 1], dot);
            dot = fmaf(kk.z, qv[4 * c4 + 2], dot);
            dot = fmaf(kk.w, qv[4 * c4 + 3], dot);
        }
        float d2 = __fsub_rn(__fadd_rn(q2, sk2[n]), __fmul_rn(2.0f, dot));
        float dist = sqrtf(fmaxf(d2, 0.0f));
        float wm = weight_at(x, y, skx[n], sky[n]);
        wout[(size_t)n * HW] = __fmul_rn(dist, wm);
    }
}

// load 6 columns (tj0-1 .. tj0+4, clamped) of one smem row
__device__ __forceinline__ void load6(const float* __restrict__ row, int tj0,
                                      float (&c)[6]) {
    float4 m = *reinterpret_cast<const float4*>(row + tj0);
    c[0] = (tj0 > 0)  ? row[tj0 - 1] : m.x;
    c[1] = m.x; c[2] = m.y; c[3] = m.z; c[4] = m.w;
    c[5] = (tj0 < 60) ? row[tj0 + 4] : m.w;
}

// y-interp value for phase r, column c (bit-exact round-6 chain)
__device__ __forceinline__ float yinterp(int r, bool t0, bool t63,
                                         float u, float ce, float d) {
    if (r == 0) return t0  ? ce : fmaf(0.625f, ce, __fmul_rn(0.375f, u));
    if (r == 1) return t0  ? ce : fmaf(0.875f, ce, __fmul_rn(0.125f, u));
    if (r == 2) return t63 ? ce : fmaf(0.125f, d, __fmul_rn(0.875f, ce));
    return             t63 ? ce : fmaf(0.375f, d, __fmul_rn(0.625f, ce));
}

// bit-exact recompute of the output quad at flat index pbase (cold path)
__device__ __forceinline__ float4 quad_at(const float* __restrict__ sw, int pbase) {
    int row_out = pbase >> 8, col_out = pbase & 255;
    int ti = row_out >> 2, r = row_out & 3;
    int tj = col_out >> 2, k = tj & 3, tj0 = tj - k;
    int yU = (ti > 0) ? ti - 1 : 0;
    int yD = (ti < 63) ? ti + 1 : 63;
    float cU[6], cC[6], cD[6];
    load6(sw + yU * 64, tj0, cU);
    load6(sw + ti * 64, tj0, cC);
    load6(sw + yD * 64, tj0, cD);
    bool t0 = (ti == 0), t63 = (ti == 63);
    float vy[6];
#pragma unroll
    for (int c = 0; c < 6; c++) vy[c] = yinterp(r, t0, t63, cU[c], cC[c], cD[c]);
    float vL = vy[k], vC = vy[k + 1], vR = vy[k + 2];
    bool e0 = (tj == 0), e63 = (tj == 63);
    float o0 = e0  ? vC : fmaf(0.625f, vC, __fmul_rn(0.375f, vL));
    float o1 = e0  ? vC : fmaf(0.875f, vC, __fmul_rn(0.125f, vL));
    float o2 = e63 ? vC : fmaf(0.125f, vR, __fmul_rn(0.875f, vC));
    float o3 = e63 ? vC : fmaf(0.375f, vR, __fmul_rn(0.625f, vC));
    return make_float4(o0, o1, o2, o3);
}

// ---------------- Kernel B: upsample + argmins + outputs ----------------
// Phase 2 processes a 4-pixel x-tile per thread: shares smem loads and
// y-interp across the tile (-40% instructions vs round 6). Quad-granular
// min; element resolved by one bit-exact recompute. Visit order is strictly
// pbase-ascending per thread -> strict < keeps first occurrence.
__global__ void __launch_bounds__(256, 8) kB(const float* __restrict__ q,
                                             const float* __restrict__ keys,
                                             float* __restrict__ out) {
    const int bn = blockIdx.x;
    const int b  = bn / NN;
    const int t  = threadIdx.x;

    __shared__ float sw[64 * 64];
    __shared__ float rv[256];
    __shared__ int   ri[256];
    __shared__ int   s_idx0, s_valid;
    __shared__ float s_mind;

    // phase 1 (round-6 exact): load wdist, min/argmin first occurrence
    const float* src = g_wdist + (size_t)bn * HW;
    float bv = 3.0e38f; int bi = 0;
    for (int k = 0; k < 16; k++) {
        int idx = k * 256 + t;
        float v = src[idx];
        sw[idx] = v;
        if (v < bv) { bv = v; bi = idx; }
    }
    rv[t] = bv; ri[t] = bi;
    __syncthreads();
    for (int s = 128; s > 0; s >>= 1) {
        if (t < s) {
            float v2 = rv[t + s]; int i2 = ri[t + s];
            if (v2 < rv[t] || (v2 == rv[t] && i2 < ri[t])) { rv[t] = v2; ri[t] = i2; }
        }
        __syncthreads();
    }
    if (t == 0) { s_mind = rv[0]; s_idx0 = ri[0]; }
    __syncthreads();

    // phase 2: tiled upsample
    float* od = out + OFF_D + (size_t)bn * 65536;
    const int j   = t & 15;
    const int tj0 = j * 4;
    float bv2 = 3.0e38f; int bqb = 0;
#pragma unroll 1
    for (int it = 0; it < 4; it++) {
        int ti = it * 16 + (t >> 4);
        int yU = (ti > 0) ? ti - 1 : 0;
        int yD = (ti < 63) ? ti + 1 : 63;
        float cU[6], cC[6], cD[6];
        load6(sw + yU * 64, tj0, cU);
        load6(sw + ti * 64, tj0, cC);
        load6(sw + yD * 64, tj0, cD);
        bool t0 = (ti == 0), t63 = (ti == 63);
        int rowb = (4 * ti) * 256 + 4 * tj0;
#pragma unroll
        for (int r = 0; r < 4; r++) {
            float vy[6];
#pragma unroll
            for (int c = 0; c < 6; c++)
                vy[c] = yinterp(r, t0, t63, cU[c], cC[c], cD[c]);
            int pb = rowb + r * 256;
#pragma unroll
            for (int k = 0; k < 4; k++) {
                float vL = vy[k], vC = vy[k + 1], vR = vy[k + 2];
                bool e0  = (tj0 == 0)  && (k == 0);
                bool e63 = (tj0 == 60) && (k == 3);
                float o0 = e0  ? vC : fmaf(0.625f, vC, __fmul_rn(0.375f, vL));
                float o1 = e0  ? vC : fmaf(0.875f, vC, __fmul_rn(0.125f, vL));
                float o2 = e63 ? vC : fmaf(0.125f, vR, __fmul_rn(0.875f, vC));
                float o3 = e63 ? vC : fmaf(0.375f, vR, __fmul_rn(0.625f, vC));
                int pbase = pb + 4 * k;
                *reinterpret_cast<float4*>(od + pbase) = make_float4(o0, o1, o2, o3);
                float qm = fminf(fminf(o0, o1), fminf(o2, o3));
                if (qm < bv2) { bv2 = qm; bqb = pbase; }   // ascending pbase
            }
        }
    }
    // resolve element within winning quad (bit-exact recompute, cold)
    {
        float4 v = quad_at(sw, bqb);
        int ei = bqb + ((v.x == bv2) ? 0 : (v.y == bv2) ? 1 : (v.z == bv2) ? 2 : 3);
        __syncthreads();
        rv[t] = bv2; ri[t] = ei;
    }
    __syncthreads();
    for (int s = 128; s > 0; s >>= 1) {
        if (t < s) {
            float v2 = rv[t + s]; int i2 = ri[t + s];
            if (v2 < rv[t] || (v2 == rv[t] && i2 < ri[t])) { rv[t] = v2; ri[t] = i2; }
        }
        __syncthreads();
    }

    if (t == 0) {
        int sidx = ri[0];
        bool nonzero = false;
        for (int c = 0; c < CC; c++) nonzero |= (keys[bn * CC + c] != 0.0f);
        bool valid = nonzero && ((int)floorf(s_mind) <= 5);
        s_valid = valid ? 1 : 0;
        int sv = valid ? (sidx >> 8)  : -1;
        int sh = valid ? (sidx & 255) : -1;
        out[OFF_J + bn * 2 + 0] = (float)sv;
        out[OFF_J + bn * 2 + 1] = (float)sh;
        out[OFF_V + bn] = valid ? 1.0f : 0.0f;
    }
    __syncthreads();
    if (t < CC) {
        float nk = s_valid ? q[((size_t)b * CC + t) * HW + s_idx0]
                           : keys[bn * CC + t];
        out[OFF_K + bn * CC + t] = nk;
    }
}

extern "C" void kernel_launch(void* const* d_in, const int* in_sizes, int n_in,
                              void* d_out, int out_size) {
    const float* q      = (const float*)d_in[0];
    const float* keys   = (const float*)d_in[1];
    const int*   joints = (const int*)  d_in[2];
    float* out = (float*)d_out;

    dim3 gA(8, BB);
    kA<<<gA, 512>>>(q, keys, joints);
    kB<<<BB * NN, 256>>>(q, keys, out);
}

// round 13
// speedup vs baseline: 2.1325x; 2.1325x over previous
#include <cuda_runtime.h>
#include <math.h>

#define BB 64
#define NN 17
#define CC 32
#define HW 4096   // 64*64

#define OFF_J 0           // joints: 64*17*2 = 2176
#define OFF_V 2176        // valid:  64*17   = 1088
#define OFF_K 3264        // new_keys: 64*17*32 = 34816
#define OFF_D 38080       // dist_x4: 64*17*256*256 = 71303168

__device__ float g_wdist[(size_t)BB * NN * HW];

// Proven-equal closed form of the 15-move ring weight (validated rounds 11/12):
//   M = max(dx,dy); w = 0.5+0.25*M for 1<=M<=15;
//   M==0 -> 0.75 iff keypoint on any border else 10; M>15 -> 10.
__device__ __forceinline__ float weight_at(int x, int y, int kx, int ky) {
    int dx = abs(x - kx), dy = abs(y - ky);
    int M = max(dx, dy);
    bool border = (kx == 0) | (kx == 63) | (ky == 0) | (ky == 63);
    if (M == 0) return border ? 0.75f : 10.0f;
    return (M <= 15) ? fmaf(0.25f, (float)M, 0.5f) : 10.0f;
}

// ---------------- Kernel A: wdist (B,N,64,64) ----------------
// Round-6 monolithic structure (high MLP: 32 q loads in flight) + cheap weight.
// Measured 21.2 us in round 12.
__global__ void __launch_bounds__(512) kA(const float* __restrict__ q,
                                          const float* __restrict__ keys,
                                          const int*   __restrict__ joints) {
    const int b = blockIdx.y;
    const int p = blockIdx.x * 512 + threadIdx.x;
    __shared__ __align__(16) float skey[NN][CC];
    __shared__ float sk2[NN];
    __shared__ int   skx[NN], sky[NN];
    const int t = threadIdx.x;
    if (t < NN * CC / 4)
        reinterpret_cast<float4*>(skey)[t] =
            reinterpret_cast<const float4*>(keys + b * NN * CC)[t];
    __syncthreads();
    if (t < NN) {
        float s = 0.f;   // mul+add sequential, no fma (XLA-faithful)
        for (int c = 0; c < CC; c++) s = __fadd_rn(s, __fmul_rn(skey[t][c], skey[t][c]));
        sk2[t] = s;
        skx[t] = joints[(b * NN + t) * 2 + 0];
        sky[t] = joints[(b * NN + t) * 2 + 1];
    }
    __syncthreads();

    float qv[CC];
    const float* qb = q + (size_t)b * CC * HW + p;
    float q2 = 0.f;
#pragma unroll
    for (int c = 0; c < CC; c++) {
        qv[c] = qb[(size_t)c * HW];
        q2 = __fadd_rn(q2, __fmul_rn(qv[c], qv[c]));
    }

    const int y = p >> 6, x = p & 63;
    float* wout = g_wdist + ((size_t)b * NN) * HW + p;
#pragma unroll 1
    for (int n = 0; n < NN; n++) {
        const float4* k4 = reinterpret_cast<const float4*>(skey[n]);
        float dot = 0.f;   // sequential ascending-c fmaf (gemm-faithful)
#pragma unroll
        for (int c4 = 0; c4 < CC / 4; c4++) {
            float4 kk = k4[c4];
            dot = fmaf(kk.x, qv[4 * c4 + 0], dot);
            dot = fmaf(kk.y, qv[4 * c4 + 1], dot);
            dot = fmaf(kk.z, qv[4 * c4 + 2], dot);
            dot = fmaf(kk.w, qv[4 * c4 + 3], dot);
        }
        float d2 = __fsub_rn(__fadd_rn(q2, sk2[n]), __fmul_rn(2.0f, dot));
        float dist = sqrtf(fmaxf(d2, 0.0f));
        float wm = weight_at(x, y, skx[n], sky[n]);
        wout[(size_t)n * HW] = __fmul_rn(dist, wm);
    }
}

// ---------------- Kernel B: upsample + argmins + outputs ----------------
// ROUND-6 EXACT (best measured: 55.5 us). Do not restructure — rounds
// 5/7/8/9/12 all regressed it.
__global__ void __launch_bounds__(256, 8) kB(const float* __restrict__ q,
                                             const float* __restrict__ keys,
                                             float* __restrict__ out) {
    const int bn = blockIdx.x;          // b*17+n
    const int b  = bn / NN;
    const int t  = threadIdx.x;

    __shared__ float sw[64 * 64];
    __shared__ float rv[256];
    __shared__ int   ri[256];
    __shared__ int   s_idx0, s_valid;
    __shared__ float s_mind;

    // phase 1: load wdist, track min/argmin (first occurrence)
    const float* src = g_wdist + (size_t)bn * HW;
    float bv = 3.0e38f; int bi = 0;
    for (int k = 0; k < 16; k++) {
        int idx = k * 256 + t;          // ascending per-thread -> strict <
        float v = src[idx];
        sw[idx] = v;
        if (v < bv) { bv = v; bi = idx; }
    }
    rv[t] = bv; ri[t] = bi;
    __syncthreads();
    for (int s = 128; s > 0; s >>= 1) {
        if (t < s) {
            float v2 = rv[t + s]; int i2 = ri[t + s];
            if (v2 < rv[t] || (v2 == rv[t] && i2 < ri[t])) { rv[t] = v2; ri[t] = i2; }
        }
        __syncthreads();
    }
    if (t == 0) { s_mind = rv[0]; s_idx0 = ri[0]; }
    __syncthreads();

    // phase 2: 4x bilinear upsample, gemm-faithful scalar arithmetic
    float* od = out + OFF_D + (size_t)bn * 65536;
    float bv2 = 3.0e38f; int bi2 = 0;
    for (int it = 0; it < 16; it++) {
        int T = it * 256 + t;
        int ti = T >> 6, tj = T & 63;
        int yU = (ti > 0) ? ti - 1 : 0;
        int yD = (ti < 63) ? ti + 1 : 63;
        int xL = (tj > 0) ? tj - 1 : 0;
        int xR = (tj < 63) ? tj + 1 : 63;

        float up[3] = { sw[yU * 64 + xL], sw[yU * 64 + tj], sw[yU * 64 + xR] };
        float ce[3] = { sw[ti * 64 + xL], sw[ti * 64 + tj], sw[ti * 64 + xR] };
        float dn[3] = { sw[yD * 64 + xL], sw[yD * 64 + tj], sw[yD * 64 + xR] };

        float vy[4][3];
#pragma unroll
        for (int c3 = 0; c3 < 3; c3++) {
            if (ti == 0) { vy[0][c3] = ce[c3]; vy[1][c3] = ce[c3]; }
            else {
                vy[0][c3] = fmaf(0.625f, ce[c3], __fmul_rn(0.375f, up[c3]));
                vy[1][c3] = fmaf(0.875f, ce[c3], __fmul_rn(0.125f, up[c3]));
            }
            if (ti == 63) { vy[2][c3] = ce[c3]; vy[3][c3] = ce[c3]; }
            else {
                vy[2][c3] = fmaf(0.125f, dn[c3], __fmul_rn(0.875f, ce[c3]));
                vy[3][c3] = fmaf(0.375f, dn[c3], __fmul_rn(0.625f, ce[c3]));
            }
        }
#pragma unroll
        for (int r = 0; r < 4; r++) {
            float vL = vy[r][0], vC = vy[r][1], vR = vy[r][2];
            float o0, o1, o2, o3;
            if (tj == 0) { o0 = vC; o1 = vC; }
            else {
                o0 = fmaf(0.625f, vC, __fmul_rn(0.375f, vL));
                o1 = fmaf(0.875f, vC, __fmul_rn(0.125f, vL));
            }
            if (tj == 63) { o2 = vC; o3 = vC; }
            else {
                o2 = fmaf(0.125f, vR, __fmul_rn(0.875f, vC));
                o3 = fmaf(0.375f, vR, __fmul_rn(0.625f, vC));
            }
            int pbase = (4 * ti + r) * 256 + 4 * tj;
            *reinterpret_cast<float4*>(od + pbase) = make_float4(o0, o1, o2, o3);
            if (o0 < bv2) { bv2 = o0; bi2 = pbase; }
            if (o1 < bv2) { bv2 = o1; bi2 = pbase + 1; }
            if (o2 < bv2) { bv2 = o2; bi2 = pbase + 2; }
            if (o3 < bv2) { bv2 = o3; bi2 = pbase + 3; }
        }
    }

    __syncthreads();
    rv[t] = bv2; ri[t] = bi2;
    __syncthreads();
    for (int s = 128; s > 0; s >>= 1) {
        if (t < s) {
            float v2 = rv[t + s]; int i2 = ri[t + s];
            if (v2 < rv[t] || (v2 == rv[t] && i2 < ri[t])) { rv[t] = v2; ri[t] = i2; }
        }
        __syncthreads();
    }

    if (t == 0) {
        int sidx = ri[0];
        bool nonzero = false;
        for (int c = 0; c < CC; c++) nonzero |= (keys[bn * CC + c] != 0.0f);
        bool valid = nonzero && ((int)floorf(s_mind) <= 5);
        s_valid = valid ? 1 : 0;
        int sv = valid ? (sidx >> 8)  : -1;
        int sh = valid ? (sidx & 255) : -1;
        out[OFF_J + bn * 2 + 0] = (float)sv;
        out[OFF_J + bn * 2 + 1] = (float)sh;
        out[OFF_V + bn] = valid ? 1.0f : 0.0f;
    }
    __syncthreads();
    if (t < CC) {
        float nk = s_valid ? q[((size_t)b * CC + t) * HW + s_idx0]
                           : keys[bn * CC + t];
        out[OFF_K + bn * CC + t] = nk;
    }
}

extern "C" void kernel_launch(void* const* d_in, const int* in_sizes, int n_in,
                              void* d_out, int out_size) {
    const float* q      = (const float*)d_in[0];
    const float* keys   = (const float*)d_in[1];
    const int*   joints = (const int*)  d_in[2];
    float* out = (float*)d_out;

    dim3 gA(8, BB);
    kA<<<gA, 512>>>(q, keys, joints);
    kB<<<BB * NN, 256>>>(q, keys, out);
}

// round 14
// speedup vs baseline: 2.1886x; 1.0263x over previous
#include <cuda_runtime.h>
#include <math.h>

#define BB 64
#define NN 17
#define CC 32
#define HW 4096   // 64*64

#define OFF_J 0           // joints: 64*17*2 = 2176
#define OFF_V 2176        // valid:  64*17   = 1088
#define OFF_K 3264        // new_keys: 64*17*32 = 34816
#define OFF_D 38080       // dist_x4: 64*17*256*256 = 71303168

__device__ float g_wdist[(size_t)BB * NN * HW];

// Proven-equal closed form of the 15-move ring weight (validated rounds 11-13):
//   M = max(dx,dy); w = 0.5+0.25*M for 1<=M<=15;
//   M==0 -> 0.75 iff keypoint on any border else 10; M>15 -> 10.
__device__ __forceinline__ float weight_at(int x, int y, int kx, int ky) {
    int dx = abs(x - kx), dy = abs(y - ky);
    int M = max(dx, dy);
    bool border = (kx == 0) | (kx == 63) | (ky == 0) | (ky == 63);
    if (M == 0) return border ? 0.75f : 10.0f;
    return (M <= 15) ? fmaf(0.25f, (float)M, 0.5f) : 10.0f;
}

// ---------------- Kernel A: wdist (B,N,64,64) ----------------
// Round-13 structure; n-loop unrolled x2 -> two independent fmaf chains in
// flight (halves exposed RAW latency of the 32-deep sequential dot chain).
// Per-n arithmetic order unchanged -> bit-identical.
__global__ void __launch_bounds__(512) kA(const float* __restrict__ q,
                                          const float* __restrict__ keys,
                                          const int*   __restrict__ joints) {
    const int b = blockIdx.y;
    const int p = blockIdx.x * 512 + threadIdx.x;
    __shared__ __align__(16) float skey[NN][CC];
    __shared__ float sk2[NN];
    __shared__ int   skx[NN], sky[NN];
    const int t = threadIdx.x;
    if (t < NN * CC / 4)
        reinterpret_cast<float4*>(skey)[t] =
            reinterpret_cast<const float4*>(keys + b * NN * CC)[t];
    __syncthreads();
    if (t < NN) {
        float s = 0.f;   // mul+add sequential, no fma (XLA-faithful)
        for (int c = 0; c < CC; c++) s = __fadd_rn(s, __fmul_rn(skey[t][c], skey[t][c]));
        sk2[t] = s;
        skx[t] = joints[(b * NN + t) * 2 + 0];
        sky[t] = joints[(b * NN + t) * 2 + 1];
    }
    __syncthreads();

    float qv[CC];
    const float* qb = q + (size_t)b * CC * HW + p;
    float q2 = 0.f;
#pragma unroll
    for (int c = 0; c < CC; c++) {
        qv[c] = qb[(size_t)c * HW];
        q2 = __fadd_rn(q2, __fmul_rn(qv[c], qv[c]));
    }

    const int y = p >> 6, x = p & 63;
    float* wout = g_wdist + ((size_t)b * NN) * HW + p;
#pragma unroll 2
    for (int n = 0; n < NN; n++) {
        const float4* k4 = reinterpret_cast<const float4*>(skey[n]);
        float dot = 0.f;   // sequential ascending-c fmaf (gemm-faithful)
#pragma unroll
        for (int c4 = 0; c4 < CC / 4; c4++) {
            float4 kk = k4[c4];
            dot = fmaf(kk.x, qv[4 * c4 + 0], dot);
            dot = fmaf(kk.y, qv[4 * c4 + 1], dot);
            dot = fmaf(kk.z, qv[4 * c4 + 2], dot);
            dot = fmaf(kk.w, qv[4 * c4 + 3], dot);
        }
        float d2 = __fsub_rn(__fadd_rn(q2, sk2[n]), __fmul_rn(2.0f, dot));
        float dist = sqrtf(fmaxf(d2, 0.0f));
        float wm = weight_at(x, y, skx[n], sky[n]);
        wout[(size_t)n * HW] = __fmul_rn(dist, wm);
    }
}

// ---------------- Kernel B: upsample + argmins + outputs ----------------
// Round-6 hot loops byte-identical; BOTH block reductions deferred to after
// the store loop so the dist_x4 write stream starts immediately.
__global__ void __launch_bounds__(256, 8) kB(const float* __restrict__ q,
                                             const float* __restrict__ keys,
                                             float* __restrict__ out) {
    const int bn = blockIdx.x;          // b*17+n
    const int b  = bn / NN;
    const int t  = threadIdx.x;

    __shared__ float sw[64 * 64];
    __shared__ float rv[256];
    __shared__ int   ri[256];
    __shared__ int   s_valid;

    // phase 1: load wdist, per-thread min/argmin (no reduction yet)
    const float* src = g_wdist + (size_t)bn * HW;
    float bv = 3.0e38f; int bi = 0;
    for (int k = 0; k < 16; k++) {
        int idx = k * 256 + t;          // ascending per-thread -> strict <
        float v = src[idx];
        sw[idx] = v;
        if (v < bv) { bv = v; bi = idx; }
    }
    __syncthreads();                    // sw ready for stencil reads

    // phase 2: 4x bilinear upsample, gemm-faithful scalar arithmetic
    float* od = out + OFF_D + (size_t)bn * 65536;
    float bv2 = 3.0e38f; int bi2 = 0;
    for (int it = 0; it < 16; it++) {
        int T = it * 256 + t;
        int ti = T >> 6, tj = T & 63;
        int yU = (ti > 0) ? ti - 1 : 0;
        int yD = (ti < 63) ? ti + 1 : 63;
        int xL = (tj > 0) ? tj - 1 : 0;
        int xR = (tj < 63) ? tj + 1 : 63;

        float up[3] = { sw[yU * 64 + xL], sw[yU * 64 + tj], sw[yU * 64 + xR] };
        float ce[3] = { sw[ti * 64 + xL], sw[ti * 64 + tj], sw[ti * 64 + xR] };
        float dn[3] = { sw[yD * 64 + xL], sw[yD * 64 + tj], sw[yD * 64 + xR] };

        float vy[4][3];
#pragma unroll
        for (int c3 = 0; c3 < 3; c3++) {
            if (ti == 0) { vy[0][c3] = ce[c3]; vy[1][c3] = ce[c3]; }
            else {
                vy[0][c3] = fmaf(0.625f, ce[c3], __fmul_rn(0.375f, up[c3]));
                vy[1][c3] = fmaf(0.875f, ce[c3], __fmul_rn(0.125f, up[c3]));
            }
            if (ti == 63) { vy[2][c3] = ce[c3]; vy[3][c3] = ce[c3]; }
            else {
                vy[2][c3] = fmaf(0.125f, dn[c3], __fmul_rn(0.875f, ce[c3]));
                vy[3][c3] = fmaf(0.375f, dn[c3], __fmul_rn(0.625f, ce[c3]));
            }
        }
#pragma unroll
        for (int r = 0; r < 4; r++) {
            float vL = vy[r][0], vC = vy[r][1], vR = vy[r][2];
            float o0, o1, o2, o3;
            if (tj == 0) { o0 = vC; o1 = vC; }
            else {
                o0 = fmaf(0.625f, vC, __fmul_rn(0.375f, vL));
                o1 = fmaf(0.875f, vC, __fmul_rn(0.125f, vL));
            }
            if (tj == 63) { o2 = vC; o3 = vC; }
            else {
                o2 = fmaf(0.125f, vR, __fmul_rn(0.875f, vC));
                o3 = fmaf(0.375f, vR, __fmul_rn(0.625f, vC));
            }
            int pbase = (4 * ti + r) * 256 + 4 * tj;
            *reinterpret_cast<float4*>(od + pbase) = make_float4(o0, o1, o2, o3);
            if (o0 < bv2) { bv2 = o0; bi2 = pbase; }
            if (o1 < bv2) { bv2 = o1; bi2 = pbase + 1; }
            if (o2 < bv2) { bv2 = o2; bi2 = pbase + 2; }
            if (o3 < bv2) { bv2 = o3; bi2 = pbase + 3; }
        }
    }

    // ---- deferred reduction 1 (wdist min/argmin) ----
    __syncthreads();
    rv[t] = bv; ri[t] = bi;
    __syncthreads();
    for (int s = 128; s > 0; s >>= 1) {
        if (t < s) {
            float v2 = rv[t + s]; int i2 = ri[t + s];
            if (v2 < rv[t] || (v2 == rv[t] && i2 < ri[t])) { rv[t] = v2; ri[t] = i2; }
        }
        __syncthreads();
    }
    const float gmin1 = rv[0];
    const int   idx1  = ri[0];
    __syncthreads();

    // ---- deferred reduction 2 (dist_x4 min/argmin) ----
    rv[t] = bv2; ri[t] = bi2;
    __syncthreads();
    for (int s = 128; s > 0; s >>= 1) {
        if (t < s) {
            float v2 = rv[t + s]; int i2 = ri[t + s];
            if (v2 < rv[t] || (v2 == rv[t] && i2 < ri[t])) { rv[t] = v2; ri[t] = i2; }
        }
        __syncthreads();
    }

    if (t == 0) {
        int sidx = ri[0];
        bool nonzero = false;
        for (int c = 0; c < CC; c++) nonzero |= (keys[bn * CC + c] != 0.0f);
        bool valid = nonzero && ((int)floorf(gmin1) <= 5);
        s_valid = valid ? 1 : 0;
        int sv = valid ? (sidx >> 8)  : -1;
        int sh = valid ? (sidx & 255) : -1;
        out[OFF_J + bn * 2 + 0] = (float)sv;
        out[OFF_J + bn * 2 + 1] = (float)sh;
        out[OFF_V + bn] = valid ? 1.0f : 0.0f;
    }
    __syncthreads();
    if (t < CC) {
        float nk = s_valid ? q[((size_t)b * CC + t) * HW + idx1]
                           : keys[bn * CC + t];
        out[OFF_K + bn * CC + t] = nk;
    }
}

extern "C" void kernel_launch(void* const* d_in, const int* in_sizes, int n_in,
                              void* d_out, int out_size) {
    const float* q      = (const float*)d_in[0];
    const float* keys   = (const float*)d_in[1];
    const int*   joints = (const int*)  d_in[2];
    float* out = (float*)d_out;

    dim3 gA(8, BB);
    kA<<<gA, 512>>>(q, keys, joints);
    kB<<<BB * NN, 256>>>(q, keys, out);
}